// round 16
// baseline (speedup 1.0000x reference)
#include <cuda_runtime.h>
#include <cstdint>
#include <math_constants.h>

#define DCOLS 2048
#define THREADS 128
#define EPT 16          // elements per thread
#define CAP 256

__device__ __forceinline__ float michelot_list(const float* c, int k) {
    // Exact sparsemax threshold over candidate list c[0..k) (all finite, > max-1).
    float S = 0.f;
    for (int i = 0; i < k; i++) S += c[i];
    float tau = (S - 1.0f) / (float)k;
    int prevc = k;
    for (int it = 0; it < CAP + 2; it++) {
        float s = 0.f; int cc = 0;
        for (int i = 0; i < k; i++) {
            float z = c[i];
            if (z > tau) { s += z; cc++; }
        }
        if (cc == prevc || cc == 0) break;
        tau = (s - 1.0f) / (float)cc;
        prevc = cc;
    }
    return tau;
}

__device__ float michelot_row_global(const float* xr, const int* mr) {
    // Fallback (statistically unreachable): serial Michelot over full row.
    float S = 0.f; int k = 0;
    for (int i = 0; i < DCOLS; i++) if (mr[i]) { S += xr[i]; k++; }
    float tau = (S - 1.0f) / (float)k;
    int prevc = k;
    for (int it = 0; it < DCOLS + 2; it++) {
        float s = 0.f; int cc = 0;
        for (int i = 0; i < DCOLS; i++) {
            if (mr[i]) { float z = xr[i]; if (z > tau) { s += z; cc++; } }
        }
        if (cc == prevc || cc == 0) break;
        tau = (s - 1.0f) / (float)cc;
        prevc = cc;
    }
    return tau;
}

__global__ __launch_bounds__(THREADS, 16) void sparsemax_kernel(
    const float* __restrict__ x,
    const int* __restrict__ mask,
    float* __restrict__ out)
{
    const int row = blockIdx.x;
    const int t = threadIdx.x;
    const int warp = t >> 5, lane = t & 31;

    const float4* xr = reinterpret_cast<const float4*>(x + (size_t)row * DCOLS);
    const int4*   mr = reinterpret_cast<const int4*>(mask + (size_t)row * DCOLS);
    float4* orow = reinterpret_cast<float4*>(out + (size_t)row * DCOLS);

    __shared__ float s_wmax[4];
    __shared__ int   s_cnt;
    __shared__ float s_tau;
    __shared__ float s_cand[CAP];

    // Load 16 values + 16 mask words per thread, fold mask: inactive -> -inf.
    float vals[EPT];
    #pragma unroll
    for (int j = 0; j < 4; j++) {
        float4 v = xr[t + j * THREADS];
        int4   m = mr[t + j * THREADS];
        vals[j * 4 + 0] = m.x ? v.x : -CUDART_INF_F;
        vals[j * 4 + 1] = m.y ? v.y : -CUDART_INF_F;
        vals[j * 4 + 2] = m.z ? v.z : -CUDART_INF_F;
        vals[j * 4 + 3] = m.w ? v.w : -CUDART_INF_F;
    }

    // ---- Phase 1: block max (max alone decides: max is always a candidate) ----
    float mx = vals[0];
    #pragma unroll
    for (int i = 1; i < EPT; i++) mx = fmaxf(mx, vals[i]);
    #pragma unroll
    for (int o = 16; o; o >>= 1)
        mx = fmaxf(mx, __shfl_xor_sync(0xFFFFFFFFu, mx, o));
    if (lane == 0) s_wmax[warp] = mx;
    if (t == 0) s_cnt = 0;
    __syncthreads();
    float allmax = fmaxf(fmaxf(s_wmax[0], s_wmax[1]), fmaxf(s_wmax[2], s_wmax[3]));

    // ---- Phase 2: warp-aggregated compaction of {v > max-1} ----
    // (if row is all-inactive: allmax=-inf, thresh=-inf, -inf > -inf false -> k=0)
    const float thresh = allmax - 1.0f;
    #pragma unroll
    for (int i = 0; i < EPT; i++) {
        const bool p = vals[i] > thresh;
        const unsigned b = __ballot_sync(0xFFFFFFFFu, p);
        if (b) {
            const int leader = __ffs(b) - 1;
            int base = 0;
            if (lane == leader) base = atomicAdd(&s_cnt, __popc(b));
            base = __shfl_sync(0xFFFFFFFFu, base, leader);
            if (p) {
                int idx = base + __popc(b & ((1u << lane) - 1u));
                if (idx < CAP) s_cand[idx] = vals[i];
            }
        }
    }
    __syncthreads();
    const int k = s_cnt;

    // ---- Phase 3: exact threshold (serial, tiny candidate set) ----
    if (t == 0) {
        float tau;
        if (k == 0)        tau = CUDART_INF_F;            // all-inactive row -> zeros
        else if (k <= CAP) tau = michelot_list(s_cand, k);
        else               tau = michelot_row_global(x + (size_t)row * DCOLS,
                                                     mask + (size_t)row * DCOLS);
        s_tau = tau;
    }
    __syncthreads();
    const float tau = s_tau;

    // ---- Phase 4: p = relu(v - tau); -inf entries give 0 automatically ----
    #pragma unroll
    for (int j = 0; j < 4; j++) {
        float4 o;
        o.x = fmaxf(vals[j * 4 + 0] - tau, 0.f);
        o.y = fmaxf(vals[j * 4 + 1] - tau, 0.f);
        o.z = fmaxf(vals[j * 4 + 2] - tau, 0.f);
        o.w = fmaxf(vals[j * 4 + 3] - tau, 0.f);
        orow[t + j * THREADS] = o;
    }
}

extern "C" void kernel_launch(void* const* d_in, const int* in_sizes, int n_in,
                              void* d_out, int out_size) {
    const float* x = (const float*)d_in[0];
    const int* mask = (const int*)d_in[1];
    float* out = (float*)d_out;

    const int rows = out_size / DCOLS;   // 16384
    sparsemax_kernel<<<rows, THREADS>>>(x, mask, out);
}